// round 10
// baseline (speedup 1.0000x reference)
#include <cuda_runtime.h>
#include <cuda_bf16.h>
#include <cstdint>
#include <stdint.h>
#include <math.h>

// Problem constants
#define Dd 1024   // feature dim
#define Cc 1000   // prototypes
#define Bb 128    // batch
#define RT 1128   // Cc + Bb stacked rows
#define MP 1152   // RT padded to multiple of 64
#define KS 8      // split-K for cross-dot gemm
#define KC (Dd / KS)
#define NB 148    // persistent grid (1 CTA/SM, co-resident — validated R9)

// Scratch (device globals — no allocation allowed)
__device__ __nv_bfloat16 g_Abf[MP * Dd];   // [mu; x; 0] bf16
__device__ __nv_bfloat16 g_Bbf[Dd * Dd];   // tril(L)^T bf16 [n][k]
__device__ __nv_bfloat16 g_MAbf[MP * Dd];  // MA = [mu;x] @ tril(L)
__device__ float g_q[MP];                  // ||MA_r||^2 + 1e-6||in_r||^2
__device__ float g_bd[RT];                 // beta . in_r
__device__ float g_part[KS * Bb * Dd];     // per-z cross-dot slices
__device__ int   g_barCnt;                 // grid barrier counter (self-resetting)

// ---------------------------------------------------------------------------
// helpers
// ---------------------------------------------------------------------------
__device__ __forceinline__ void ldsm_x4(uint32_t* r, uint32_t addr) {
    asm volatile("ldmatrix.sync.aligned.m8n8.x4.shared.b16 {%0,%1,%2,%3}, [%4];\n"
                 : "=r"(r[0]), "=r"(r[1]), "=r"(r[2]), "=r"(r[3]) : "r"(addr));
}

__device__ __forceinline__ void mma_bf16(float* d, const uint32_t* a,
                                         uint32_t b0, uint32_t b1) {
    asm volatile(
        "mma.sync.aligned.m16n8k16.row.col.f32.bf16.bf16.f32 "
        "{%0,%1,%2,%3}, {%4,%5,%6,%7}, {%8,%9}, {%0,%1,%2,%3};\n"
        : "+f"(d[0]), "+f"(d[1]), "+f"(d[2]), "+f"(d[3])
        : "r"(a[0]), "r"(a[1]), "r"(a[2]), "r"(a[3]), "r"(b0), "r"(b1));
}

// Half-block barrier (128 threads): named barrier 1 or 2 (0 = __syncthreads).
__device__ __forceinline__ void hbar(int h) {
    asm volatile("bar.sync %0, 128;" :: "r"(h + 1) : "memory");
}

// Grid-wide barrier: all NB blocks co-resident (1 CTA/SM).
__device__ __forceinline__ void gridbar(int target) {
    __threadfence();
    __syncthreads();
    if (threadIdx.x == 0) {
        atomicAdd(&g_barCnt, 1);
        while (*(volatile int*)&g_barCnt < target) __nanosleep(64);
    }
    __syncthreads();
}

// ---------------------------------------------------------------------------
// Persistent mega-kernel: two independent 128-thread tile units per block
// (round-7 proven GEMM engine), phases separated by grid barriers.
// ---------------------------------------------------------------------------
__global__ __launch_bounds__(256) void mega(const float* __restrict__ x,
                                            const float* __restrict__ mu,
                                            const float* __restrict__ beta,
                                            const float* __restrict__ L,
                                            const float* __restrict__ lmbda,
                                            const float* __restrict__ scale,
                                            float* __restrict__ out) {
    __shared__ __align__(16) __nv_bfloat16 As[2][64][40];
    __shared__ __align__(16) __nv_bfloat16 Bs[2][64][40];
    __shared__ float redf[2][8];

    int bid = blockIdx.x;
    int tid = threadIdx.x;
    int lane = tid & 31, w = tid >> 5;
    int h = tid >> 7;          // half (tile unit) 0/1
    int hw = tid & 127;        // thread within half
    int hlane = hw & 31;
    int w2 = hw >> 5;          // warp within half (0..3)

    // ===================== P0: prep (full 256-thread block) =====================
    for (int u = bid; u < MP + 1024; u += NB) {
        __syncthreads();
        if (u < MP) {
            int r = u;
            int k = tid * 4;
            float4 v = make_float4(0.f, 0.f, 0.f, 0.f);
            if (r < Cc)      v = *reinterpret_cast<const float4*>(mu + (size_t)r * Dd + k);
            else if (r < RT) v = *reinterpret_cast<const float4*>(x + (size_t)(r - Cc) * Dd + k);
            __nv_bfloat162 p0 = __floats2bfloat162_rn(v.x, v.y);
            __nv_bfloat162 p1 = __floats2bfloat162_rn(v.z, v.w);
            uint2 o;
            o.x = *reinterpret_cast<uint32_t*>(&p0);
            o.y = *reinterpret_cast<uint32_t*>(&p1);
            *reinterpret_cast<uint2*>(g_Abf + (size_t)r * Dd + k) = o;

            if (r < RT) {
                float4 b4 = *reinterpret_cast<const float4*>(beta + k);
                float sin_ = v.x * v.x + v.y * v.y + v.z * v.z + v.w * v.w;
                float sb = b4.x * v.x + b4.y * v.y + b4.z * v.z + b4.w * v.w;
#pragma unroll
                for (int off = 16; off > 0; off >>= 1) {
                    sin_ += __shfl_xor_sync(0xFFFFFFFFu, sin_, off);
                    sb += __shfl_xor_sync(0xFFFFFFFFu, sb, off);
                }
                if (lane == 0) { redf[0][w] = sin_; redf[1][w] = sb; }
                __syncthreads();
                if (tid == 0) {
                    float t0 = 0.f, t1 = 0.f;
#pragma unroll
                    for (int wq = 0; wq < 8; wq++) { t0 += redf[0][wq]; t1 += redf[1][wq]; }
                    g_q[r] = 1e-6f * t0;  // seed; P1 epilogue atomically adds ||MA||^2
                    g_bd[r] = t1;
                }
            } else if (tid == 0) {
                g_q[r] = 0.f;
            }
        } else {
            // tril + transpose one 32x32 tile of L (As[0] as float scratch)
            int tileId = u - MP;
            int bx = (tileId & 31) * 32;   // k base
            int by = (tileId >> 5) * 32;   // n base
            float* tf = reinterpret_cast<float*>(&As[0][0][0]);
            int tx = tid & 31, ty = tid >> 5;
#pragma unroll
            for (int i = ty; i < 32; i += 8)
                tf[i * 33 + tx] = L[(size_t)(bx + i) * Dd + by + tx];
            __syncthreads();
#pragma unroll
            for (int i = ty; i < 32; i += 8) {
                int n = by + i, k = bx + tx;
                float v = (k >= n) ? tf[tx * 33 + i] : 0.f;
                g_Bbf[(size_t)n * Dd + k] = __float2bfloat16(v);
            }
        }
    }
    gridbar(NB);

    // ===================== P1: MA gemm (round-7 engine, per half) =====================
    // 288 tiles (18 m x 16 n) of 64x64, triangular K-skip; units = bid + NB*h.
    {
        int u = bid + NB * h;
        if (u < 288) {
            int bn = (u / 18) * 64;
            int bm = (u % 18) * 64;
            int wm = (w2 & 1) * 32, wn = (w2 >> 1) * 32;
            int lr = hw >> 1;
            int lk = (hw & 1) * 16;
            const __nv_bfloat16* aptr = g_Abf + (size_t)(bm + lr) * Dd + lk;
            const __nv_bfloat16* bptr = g_Bbf + (size_t)(bn + lr) * Dd + lk;

            float acc[2][4][4];
#pragma unroll
            for (int mt = 0; mt < 2; mt++)
#pragma unroll
                for (int nt = 0; nt < 4; nt++)
#pragma unroll
                    for (int e = 0; e < 4; e++) acc[mt][nt][e] = 0.f;

            uint32_t aA[2], bA[2];
#pragma unroll
            for (int t2 = 0; t2 < 2; t2++) {
                aA[t2] = (uint32_t)__cvta_generic_to_shared(
                    &As[h][wm + t2 * 16 + (hlane & 15)][(hlane >> 4) * 8]);
                bA[t2] = (uint32_t)__cvta_generic_to_shared(
                    &Bs[h][wn + t2 * 16 + (hlane & 15)][(hlane >> 4) * 8]);
            }

            int kstart = bn;  // tril skip
            uint4 pa0 = *reinterpret_cast<const uint4*>(aptr + kstart);
            uint4 pa1 = *reinterpret_cast<const uint4*>(aptr + kstart + 8);
            uint4 pb0 = *reinterpret_cast<const uint4*>(bptr + kstart);
            uint4 pb1 = *reinterpret_cast<const uint4*>(bptr + kstart + 8);

            for (int k0 = kstart; k0 < Dd; k0 += 32) {
                *reinterpret_cast<uint4*>(&As[h][lr][lk]) = pa0;
                *reinterpret_cast<uint4*>(&As[h][lr][lk + 8]) = pa1;
                *reinterpret_cast<uint4*>(&Bs[h][lr][lk]) = pb0;
                *reinterpret_cast<uint4*>(&Bs[h][lr][lk + 8]) = pb1;
                hbar(h);
                if (k0 + 32 < Dd) {
                    pa0 = *reinterpret_cast<const uint4*>(aptr + k0 + 32);
                    pa1 = *reinterpret_cast<const uint4*>(aptr + k0 + 40);
                    pb0 = *reinterpret_cast<const uint4*>(bptr + k0 + 32);
                    pb1 = *reinterpret_cast<const uint4*>(bptr + k0 + 40);
                }
#pragma unroll
                for (int ks = 0; ks < 2; ks++) {
                    uint32_t off = (uint32_t)(ks * 32);
                    uint32_t a0[4], a1[4], br0[4], br1[4];
                    ldsm_x4(a0, aA[0] + off);
                    ldsm_x4(a1, aA[1] + off);
                    ldsm_x4(br0, bA[0] + off);
                    ldsm_x4(br1, bA[1] + off);
#pragma unroll
                    for (int mt = 0; mt < 2; mt++) {
                        uint32_t* a = mt ? a1 : a0;
                        mma_bf16(acc[mt][0], a, br0[0], br0[2]);
                        mma_bf16(acc[mt][1], a, br0[1], br0[3]);
                        mma_bf16(acc[mt][2], a, br1[0], br1[2]);
                        mma_bf16(acc[mt][3], a, br1[1], br1[3]);
                    }
                }
                hbar(h);
            }

            int mrow = hlane >> 2;
            int ncol = (hlane & 3) * 2;
#pragma unroll
            for (int mt = 0; mt < 2; mt++) {
                float s0 = 0.f, s1 = 0.f;
                int row = bm + wm + mt * 16 + mrow;
#pragma unroll
                for (int nt = 0; nt < 4; nt++) {
                    int col = bn + wn + nt * 8 + ncol;
                    __nv_bfloat162 lo = __floats2bfloat162_rn(acc[mt][nt][0], acc[mt][nt][1]);
                    __nv_bfloat162 hi = __floats2bfloat162_rn(acc[mt][nt][2], acc[mt][nt][3]);
                    *reinterpret_cast<__nv_bfloat162*>(g_MAbf + (size_t)row * Dd + col) = lo;
                    *reinterpret_cast<__nv_bfloat162*>(g_MAbf + (size_t)(row + 8) * Dd + col) = hi;
                    float l0 = __bfloat162float(lo.x), l1 = __bfloat162float(lo.y);
                    float h0 = __bfloat162float(hi.x), h1 = __bfloat162float(hi.y);
                    s0 += l0 * l0 + l1 * l1;
                    s1 += h0 * h0 + h1 * h1;
                }
                s0 += __shfl_xor_sync(0xFFFFFFFFu, s0, 1);
                s0 += __shfl_xor_sync(0xFFFFFFFFu, s0, 2);
                s1 += __shfl_xor_sync(0xFFFFFFFFu, s1, 1);
                s1 += __shfl_xor_sync(0xFFFFFFFFu, s1, 2);
                if ((hlane & 3) == 0) {
                    atomicAdd(&g_q[row], s0);
                    atomicAdd(&g_q[row + 8], s1);
                }
            }
        }
    }
    gridbar(2 * NB);

    // ===================== P2: cross-dot gemm (per half, no atomics) =====================
    // 256 tiles: bm(2) x bn(16) x z(8); direct stores into per-z g_part slices.
    {
        int u = bid + NB * h;
        if (u < 256) {
            int bm = (u & 1) * 64;
            int bn = ((u >> 1) & 15) * 64;
            int z = u >> 5;
            int kb = z * KC;
            int wm = (w2 & 1) * 32, wn = (w2 >> 1) * 32;
            int lr = hw >> 1;
            int lk = (hw & 1) * 16;
            const __nv_bfloat16* aptr = g_MAbf + (size_t)(Cc + bm + lr) * Dd + kb + lk;
            const __nv_bfloat16* bptr = g_MAbf + (size_t)(bn + lr) * Dd + kb + lk;

            float acc[2][4][4];
#pragma unroll
            for (int mt = 0; mt < 2; mt++)
#pragma unroll
                for (int nt = 0; nt < 4; nt++)
#pragma unroll
                    for (int e = 0; e < 4; e++) acc[mt][nt][e] = 0.f;

            uint32_t aA[2], bA[2];
#pragma unroll
            for (int t2 = 0; t2 < 2; t2++) {
                aA[t2] = (uint32_t)__cvta_generic_to_shared(
                    &As[h][wm + t2 * 16 + (hlane & 15)][(hlane >> 4) * 8]);
                bA[t2] = (uint32_t)__cvta_generic_to_shared(
                    &Bs[h][wn + t2 * 16 + (hlane & 15)][(hlane >> 4) * 8]);
            }

            uint4 pa0 = *reinterpret_cast<const uint4*>(aptr);
            uint4 pa1 = *reinterpret_cast<const uint4*>(aptr + 8);
            uint4 pb0 = *reinterpret_cast<const uint4*>(bptr);
            uint4 pb1 = *reinterpret_cast<const uint4*>(bptr + 8);

#pragma unroll 1
            for (int k0 = 0; k0 < KC; k0 += 32) {
                *reinterpret_cast<uint4*>(&As[h][lr][lk]) = pa0;
                *reinterpret_cast<uint4*>(&As[h][lr][lk + 8]) = pa1;
                *reinterpret_cast<uint4*>(&Bs[h][lr][lk]) = pb0;
                *reinterpret_cast<uint4*>(&Bs[h][lr][lk + 8]) = pb1;
                hbar(h);
                if (k0 + 32 < KC) {
                    pa0 = *reinterpret_cast<const uint4*>(aptr + k0 + 32);
                    pa1 = *reinterpret_cast<const uint4*>(aptr + k0 + 40);
                    pb0 = *reinterpret_cast<const uint4*>(bptr + k0 + 32);
                    pb1 = *reinterpret_cast<const uint4*>(bptr + k0 + 40);
                }
#pragma unroll
                for (int ks = 0; ks < 2; ks++) {
                    uint32_t off = (uint32_t)(ks * 32);
                    uint32_t a0[4], a1[4], br0[4], br1[4];
                    ldsm_x4(a0, aA[0] + off);
                    ldsm_x4(a1, aA[1] + off);
                    ldsm_x4(br0, bA[0] + off);
                    ldsm_x4(br1, bA[1] + off);
#pragma unroll
                    for (int mt = 0; mt < 2; mt++) {
                        uint32_t* a = mt ? a1 : a0;
                        mma_bf16(acc[mt][0], a, br0[0], br0[2]);
                        mma_bf16(acc[mt][1], a, br0[1], br0[3]);
                        mma_bf16(acc[mt][2], a, br1[0], br1[2]);
                        mma_bf16(acc[mt][3], a, br1[1], br1[3]);
                    }
                }
                hbar(h);
            }

            int mrow = hlane >> 2;
            int ncol = (hlane & 3) * 2;
            float* outz = g_part + (size_t)z * Bb * Dd;
#pragma unroll
            for (int mt = 0; mt < 2; mt++)
#pragma unroll
                for (int nt = 0; nt < 4; nt++) {
                    int row = bm + wm + mt * 16 + mrow;
                    int col = bn + wn + nt * 8 + ncol;
                    *reinterpret_cast<float2*>(outz + (size_t)row * Dd + col) =
                        make_float2(acc[mt][nt][0], acc[mt][nt][1]);
                    *reinterpret_cast<float2*>(outz + (size_t)(row + 8) * Dd + col) =
                        make_float2(acc[mt][nt][2], acc[mt][nt][3]);
                }
        }
    }
    gridbar(3 * NB);

    // ===================== P3: finalize (full grid) =====================
    {
        float lm = *lmbda;
        float sc = *scale;
        for (int b = bid; b < Bb; b += NB) {
            if (tid < 250) {
                int c = tid * 4;
                float4 s = make_float4(0.f, 0.f, 0.f, 0.f);
#pragma unroll
                for (int z = 0; z < KS; z++) {
                    float4 p = __ldcg(reinterpret_cast<const float4*>(
                        g_part + ((size_t)z * Bb + b) * Dd + c));
                    s.x += p.x; s.y += p.y; s.z += p.z; s.w += p.w;
                }
                float4 qc = __ldcg(reinterpret_cast<const float4*>(g_q + c));
                float4 bdc = *reinterpret_cast<const float4*>(g_bd + c);
                float qb = __ldcg(g_q + Cc + b);
                float bdb = g_bd[Cc + b];
                float4 o;
                {
                    float quad = qb + qc.x - 2.f * s.x;
                    float bd = bdb - bdc.x;
                    o.x = -sc * (sqrtf(quad + 1e-6f) + lm * sqrtf(bd * bd + 1e-6f));
                }
                {
                    float quad = qb + qc.y - 2.f * s.y;
                    float bd = bdb - bdc.y;
                    o.y = -sc * (sqrtf(quad + 1e-6f) + lm * sqrtf(bd * bd + 1e-6f));
                }
                {
                    float quad = qb + qc.z - 2.f * s.z;
                    float bd = bdb - bdc.z;
                    o.z = -sc * (sqrtf(quad + 1e-6f) + lm * sqrtf(bd * bd + 1e-6f));
                }
                {
                    float quad = qb + qc.w - 2.f * s.w;
                    float bd = bdb - bdc.w;
                    o.w = -sc * (sqrtf(quad + 1e-6f) + lm * sqrtf(bd * bd + 1e-6f));
                }
                *reinterpret_cast<float4*>(out + (size_t)b * Cc + c) = o;
            }
        }
    }

    // ---- final arrival: last block resets barrier counter (replay-safe) ----
    __syncthreads();
    if (tid == 0) {
        int t = atomicAdd(&g_barCnt, 1);
        if (t == 4 * NB - 1) *(volatile int*)&g_barCnt = 0;
    }
}

// ---------------------------------------------------------------------------
extern "C" void kernel_launch(void* const* d_in, const int* in_sizes, int n_in,
                              void* d_out, int out_size) {
    const float *x = nullptr, *mu = nullptr, *beta = nullptr, *L = nullptr;
    const float *lmbda = nullptr, *scale = nullptr;
    for (int i = 0; i < n_in; i++) {
        const float* p = (const float*)d_in[i];
        switch (in_sizes[i]) {
            case Bb * Dd:  x = p; break;
            case Cc * Dd:  mu = p; break;
            case Dd:       beta = p; break;
            case Dd * Dd:  L = p; break;
            case 1:        if (!lmbda) lmbda = p; else scale = p; break;
            default: break;
        }
    }

    mega<<<NB, 256>>>(x, mu, beta, L, lmbda, scale, (float*)d_out);
}

// round 12
// speedup vs baseline: 1.0897x; 1.0897x over previous
#include <cuda_runtime.h>
#include <cuda_bf16.h>
#include <cstdint>
#include <stdint.h>
#include <math.h>

// Problem constants
#define Dd 1024   // feature dim
#define Cc 1000   // prototypes
#define Bb 128    // batch
#define RT 1128   // Cc + Bb stacked rows
#define MP 1152   // RT padded to multiple of 64
#define KS 8      // split-K for cross-dot gemm
#define KC (Dd / KS)

// Scratch (device globals — no allocation allowed)
__device__ __nv_bfloat16 g_Abf[MP * Dd];   // [mu; x; 0] bf16
__device__ __nv_bfloat16 g_Bbf[Dd * Dd];   // tril(L)^T bf16 [n][k]
__device__ __nv_bfloat16 g_MAbf[MP * Dd];  // MA = [mu;x] @ tril(L)
__device__ float g_q[MP];                  // ||MA_r||^2 + 1e-6||in_r||^2
__device__ float g_bd[RT];                 // beta . in_r
__device__ float g_part[KS * Bb * Dd];     // per-z cross-dot slices (no atomics)

// ---------------------------------------------------------------------------
// helpers
// ---------------------------------------------------------------------------
__device__ __forceinline__ void ldsm_x4(uint32_t* r, uint32_t addr) {
    asm volatile("ldmatrix.sync.aligned.m8n8.x4.shared.b16 {%0,%1,%2,%3}, [%4];\n"
                 : "=r"(r[0]), "=r"(r[1]), "=r"(r[2]), "=r"(r[3]) : "r"(addr));
}

__device__ __forceinline__ void mma_bf16(float* d, const uint32_t* a,
                                         uint32_t b0, uint32_t b1) {
    asm volatile(
        "mma.sync.aligned.m16n8k16.row.col.f32.bf16.bf16.f32 "
        "{%0,%1,%2,%3}, {%4,%5,%6,%7}, {%8,%9}, {%0,%1,%2,%3};\n"
        : "+f"(d[0]), "+f"(d[1]), "+f"(d[2]), "+f"(d[3])
        : "r"(a[0]), "r"(a[1]), "r"(a[2]), "r"(a[3]), "r"(b0), "r"(b1));
}

#define CP16(dst, src) \
    asm volatile("cp.async.cg.shared.global [%0], [%1], 16;\n" \
                 :: "r"(dst), "l"(src) : "memory")
#define CP_COMMIT() asm volatile("cp.async.commit_group;\n" ::: "memory")
#define CP_WAIT1()  asm volatile("cp.async.wait_group 1;\n" ::: "memory")
#define CP_WAIT0()  asm volatile("cp.async.wait_group 0;\n" ::: "memory")

#define BUFB 5120   // bytes per smem stage (64*40*2)

// ---------------------------------------------------------------------------
// 0) prep (block-range dispatch):
//    [0, MP):        bf16 convert row of [mu;x;0] + input stats (seed g_q, g_bd)
//    [MP, MP+1024):  tril+transpose 32x32 tile of L (SKIPPING never-read tiles)
// ---------------------------------------------------------------------------
__global__ __launch_bounds__(256) void prep(const float* __restrict__ x,
                                            const float* __restrict__ mu,
                                            const float* __restrict__ beta,
                                            const float* __restrict__ L) {
    int bid = blockIdx.x;
    int tid = threadIdx.x;

    if (bid < MP) {
        int r = bid;
        int k = tid * 4;
        float4 v = make_float4(0.f, 0.f, 0.f, 0.f);
        if (r < Cc)      v = *reinterpret_cast<const float4*>(mu + (size_t)r * Dd + k);
        else if (r < RT) v = *reinterpret_cast<const float4*>(x + (size_t)(r - Cc) * Dd + k);
        __nv_bfloat162 p0 = __floats2bfloat162_rn(v.x, v.y);
        __nv_bfloat162 p1 = __floats2bfloat162_rn(v.z, v.w);
        uint2 o;
        o.x = *reinterpret_cast<uint32_t*>(&p0);
        o.y = *reinterpret_cast<uint32_t*>(&p1);
        *reinterpret_cast<uint2*>(g_Abf + (size_t)r * Dd + k) = o;

        if (r >= RT) {
            if (tid == 0) g_q[r] = 0.f;
            return;
        }

        float4 b4 = *reinterpret_cast<const float4*>(beta + k);
        float sin_ = v.x * v.x + v.y * v.y + v.z * v.z + v.w * v.w;
        float sb = b4.x * v.x + b4.y * v.y + b4.z * v.z + b4.w * v.w;
#pragma unroll
        for (int off = 16; off > 0; off >>= 1) {
            sin_ += __shfl_xor_sync(0xFFFFFFFFu, sin_, off);
            sb += __shfl_xor_sync(0xFFFFFFFFu, sb, off);
        }
        __shared__ float red[2][8];
        int wid = tid >> 5, lane = tid & 31;
        if (lane == 0) { red[0][wid] = sin_; red[1][wid] = sb; }
        __syncthreads();
        if (tid == 0) {
            float t0 = 0.f, t1 = 0.f;
#pragma unroll
            for (int wq = 0; wq < 8; wq++) { t0 += red[0][wq]; t1 += red[1][wq]; }
            g_q[r] = 1e-6f * t0;   // seed; gemm epilogue atomically adds ||MA||^2
            g_bd[r] = t1;
        }
    } else {
        // tril + transpose one 32x32 tile of L
        int tileId = bid - MP;
        int bx = (tileId & 31) * 32;   // k base
        int by = (tileId >> 5) * 32;   // n base
        // gemm reads g_Bbf[n][k] only for k >= 64*floor(n/64): skip dead tiles
        if (bx < ((by >> 6) << 6)) return;
        __shared__ float t[32][33];
        int tx = tid & 31, ty = tid >> 5;  // 32 x 8
#pragma unroll
        for (int i = ty; i < 32; i += 8)
            t[i][tx] = L[(size_t)(bx + i) * Dd + by + tx];
        __syncthreads();
#pragma unroll
        for (int i = ty; i < 32; i += 8) {
            int n = by + i, k = bx + tx;
            float v = (k >= n) ? t[tx][i] : 0.f;
            g_Bbf[(size_t)n * Dd + k] = __float2bfloat16(v);
        }
    }
}

// ---------------------------------------------------------------------------
// 1) gemm_ma_mma: g_MAbf[m][n] = sum_k g_Abf[m][k] * g_Bbf[n][k]  (NT bf16 HMMA)
//    BM=BN=64, BK=32, 128 thr, 2x2 warps, warp tile 32x32. Triangular K-skip.
//    3-stage cp.async pipeline. NOTE: aptr/bptr already include lk; cp.async
//    offsets are pure k-multiples of 32 (the R11 bug was adding lk twice).
// ---------------------------------------------------------------------------
__global__ __launch_bounds__(128) void gemm_ma_mma() {
    __shared__ __align__(16) __nv_bfloat16 As[3][64][40];
    __shared__ __align__(16) __nv_bfloat16 Bs[3][64][40];
    int bm = blockIdx.x * 64;
    int bn = blockIdx.y * 64;
    int tid = threadIdx.x;
    int lane = tid & 31, w = tid >> 5;
    int wm = (w & 1) * 32, wn = (w >> 1) * 32;

    int lr = tid >> 1;             // 0..63 (tile row)
    int lk = (tid & 1) * 16;       // 0 / 16 (bf16 units)
    const __nv_bfloat16* aptr = g_Abf + (size_t)(bm + lr) * Dd + lk;   // includes lk
    const __nv_bfloat16* bptr = g_Bbf + (size_t)(bn + lr) * Dd + lk;   // includes lk
    uint32_t sA = (uint32_t)__cvta_generic_to_shared(&As[0][lr][lk]);
    uint32_t sB = (uint32_t)__cvta_generic_to_shared(&Bs[0][lr][lk]);

    float acc[2][4][4];
#pragma unroll
    for (int mt = 0; mt < 2; mt++)
#pragma unroll
        for (int nt = 0; nt < 4; nt++)
#pragma unroll
            for (int e = 0; e < 4; e++) acc[mt][nt][e] = 0.f;

    uint32_t aA[2], bA[2];
#pragma unroll
    for (int t2 = 0; t2 < 2; t2++) {
        aA[t2] = (uint32_t)__cvta_generic_to_shared(
            &As[0][wm + t2 * 16 + (lane & 15)][(lane >> 4) * 8]);
        bA[t2] = (uint32_t)__cvta_generic_to_shared(
            &Bs[0][wn + t2 * 16 + (lane & 15)][(lane >> 4) * 8]);
    }

    int kstart = bn;                       // tril skip
    int niter = (Dd - kstart) >> 5;        // >= 2 always

    // prologue: stages 0 and 1 (k offsets are multiples of 32 only)
    {
        CP16(sA, aptr + kstart);
        CP16(sA + 16, aptr + kstart + 8);
        CP16(sB, bptr + kstart);
        CP16(sB + 16, bptr + kstart + 8);
        CP_COMMIT();
        CP16(sA + BUFB, aptr + kstart + 32);
        CP16(sA + BUFB + 16, aptr + kstart + 40);
        CP16(sB + BUFB, bptr + kstart + 32);
        CP16(sB + BUFB + 16, bptr + kstart + 40);
        CP_COMMIT();
    }

    for (int it = 0; it < niter; ++it) {
        if (it + 2 <= niter) CP_WAIT1(); else CP_WAIT0();
        __syncthreads();
        if (it + 2 < niter) {
            int j = it + 2;
            uint32_t bo = (uint32_t)((j % 3) * BUFB);
            int k = kstart + j * 32;
            CP16(sA + bo, aptr + k);
            CP16(sA + bo + 16, aptr + k + 8);
            CP16(sB + bo, bptr + k);
            CP16(sB + bo + 16, bptr + k + 8);
            CP_COMMIT();
        }
        uint32_t bo = (uint32_t)((it % 3) * BUFB);
#pragma unroll
        for (int ks = 0; ks < 2; ks++) {
            uint32_t off = bo + (uint32_t)(ks * 32);
            uint32_t a0[4], a1[4], br0[4], br1[4];
            ldsm_x4(a0, aA[0] + off);
            ldsm_x4(a1, aA[1] + off);
            ldsm_x4(br0, bA[0] + off);
            ldsm_x4(br1, bA[1] + off);
#pragma unroll
            for (int mt = 0; mt < 2; mt++) {
                uint32_t* a = mt ? a1 : a0;
                mma_bf16(acc[mt][0], a, br0[0], br0[2]);
                mma_bf16(acc[mt][1], a, br0[1], br0[3]);
                mma_bf16(acc[mt][2], a, br1[0], br1[2]);
                mma_bf16(acc[mt][3], a, br1[1], br1[3]);
            }
        }
    }

    int mrow = lane >> 2;
    int ncol = (lane & 3) * 2;
#pragma unroll
    for (int mt = 0; mt < 2; mt++) {
        float s0 = 0.f, s1 = 0.f;   // row-norm partials of rounded values
        int row = bm + wm + mt * 16 + mrow;
#pragma unroll
        for (int nt = 0; nt < 4; nt++) {
            int col = bn + wn + nt * 8 + ncol;
            __nv_bfloat162 lo = __floats2bfloat162_rn(acc[mt][nt][0], acc[mt][nt][1]);
            __nv_bfloat162 hi = __floats2bfloat162_rn(acc[mt][nt][2], acc[mt][nt][3]);
            *reinterpret_cast<__nv_bfloat162*>(g_MAbf + (size_t)row * Dd + col) = lo;
            *reinterpret_cast<__nv_bfloat162*>(g_MAbf + (size_t)(row + 8) * Dd + col) = hi;
            float l0 = __bfloat162float(lo.x), l1 = __bfloat162float(lo.y);
            float h0 = __bfloat162float(hi.x), h1 = __bfloat162float(hi.y);
            s0 += l0 * l0 + l1 * l1;
            s1 += h0 * h0 + h1 * h1;
        }
        s0 += __shfl_xor_sync(0xFFFFFFFFu, s0, 1);
        s0 += __shfl_xor_sync(0xFFFFFFFFu, s0, 2);
        s1 += __shfl_xor_sync(0xFFFFFFFFu, s1, 1);
        s1 += __shfl_xor_sync(0xFFFFFFFFu, s1, 2);
        if ((lane & 3) == 0) {
            atomicAdd(&g_q[row], s0);
            atomicAdd(&g_q[row + 8], s1);
        }
    }
}

// ---------------------------------------------------------------------------
// 2) dot_mma: g_part[z][b][c] = sum_{k in chunk z} MAbf[Cc+b][k]*MAbf[c][k]
//    Same engine, niter=4, direct per-z stores (no atomics, no zeroing).
// ---------------------------------------------------------------------------
__global__ __launch_bounds__(128) void dot_mma() {
    __shared__ __align__(16) __nv_bfloat16 As[3][64][40];
    __shared__ __align__(16) __nv_bfloat16 Bs[3][64][40];
    int bm = blockIdx.x * 64;                // b offset
    int bn = blockIdx.y * 64;                // c offset
    int kb = blockIdx.z * KC;                // k chunk base
    int tid = threadIdx.x;
    int lane = tid & 31, w = tid >> 5;
    int wm = (w & 1) * 32, wn = (w >> 1) * 32;

    int lr = tid >> 1;
    int lk = (tid & 1) * 16;
    const __nv_bfloat16* aptr = g_MAbf + (size_t)(Cc + bm + lr) * Dd + kb + lk;  // incl lk
    const __nv_bfloat16* bptr = g_MAbf + (size_t)(bn + lr) * Dd + kb + lk;       // incl lk
    uint32_t sA = (uint32_t)__cvta_generic_to_shared(&As[0][lr][lk]);
    uint32_t sB = (uint32_t)__cvta_generic_to_shared(&Bs[0][lr][lk]);

    float acc[2][4][4];
#pragma unroll
    for (int mt = 0; mt < 2; mt++)
#pragma unroll
        for (int nt = 0; nt < 4; nt++)
#pragma unroll
            for (int e = 0; e < 4; e++) acc[mt][nt][e] = 0.f;

    uint32_t aA[2], bA[2];
#pragma unroll
    for (int t2 = 0; t2 < 2; t2++) {
        aA[t2] = (uint32_t)__cvta_generic_to_shared(
            &As[0][wm + t2 * 16 + (lane & 15)][(lane >> 4) * 8]);
        bA[t2] = (uint32_t)__cvta_generic_to_shared(
            &Bs[0][wn + t2 * 16 + (lane & 15)][(lane >> 4) * 8]);
    }

    const int niter = KC >> 5;  // 4
    {
        CP16(sA, aptr);
        CP16(sA + 16, aptr + 8);
        CP16(sB, bptr);
        CP16(sB + 16, bptr + 8);
        CP_COMMIT();
        CP16(sA + BUFB, aptr + 32);
        CP16(sA + BUFB + 16, aptr + 40);
        CP16(sB + BUFB, bptr + 32);
        CP16(sB + BUFB + 16, bptr + 40);
        CP_COMMIT();
    }

#pragma unroll
    for (int it = 0; it < niter; ++it) {
        if (it + 2 <= niter) CP_WAIT1(); else CP_WAIT0();
        __syncthreads();
        if (it + 2 < niter) {
            int j = it + 2;
            uint32_t bo = (uint32_t)((j % 3) * BUFB);
            int k = j * 32;
            CP16(sA + bo, aptr + k);
            CP16(sA + bo + 16, aptr + k + 8);
            CP16(sB + bo, bptr + k);
            CP16(sB + bo + 16, bptr + k + 8);
            CP_COMMIT();
        }
        uint32_t bo = (uint32_t)((it % 3) * BUFB);
#pragma unroll
        for (int ks = 0; ks < 2; ks++) {
            uint32_t off = bo + (uint32_t)(ks * 32);
            uint32_t a0[4], a1[4], br0[4], br1[4];
            ldsm_x4(a0, aA[0] + off);
            ldsm_x4(a1, aA[1] + off);
            ldsm_x4(br0, bA[0] + off);
            ldsm_x4(br1, bA[1] + off);
#pragma unroll
            for (int mt = 0; mt < 2; mt++) {
                uint32_t* a = mt ? a1 : a0;
                mma_bf16(acc[mt][0], a, br0[0], br0[2]);
                mma_bf16(acc[mt][1], a, br0[1], br0[3]);
                mma_bf16(acc[mt][2], a, br1[0], br1[2]);
                mma_bf16(acc[mt][3], a, br1[1], br1[3]);
            }
        }
    }

    int mrow = lane >> 2;
    int ncol = (lane & 3) * 2;
    float* outz = g_part + (size_t)blockIdx.z * Bb * Dd;
#pragma unroll
    for (int mt = 0; mt < 2; mt++)
#pragma unroll
        for (int nt = 0; nt < 4; nt++) {
            int row = bm + wm + mt * 16 + mrow;
            int col = bn + wn + nt * 8 + ncol;
            *reinterpret_cast<float2*>(outz + (size_t)row * Dd + col) =
                make_float2(acc[mt][nt][0], acc[mt][nt][1]);
            *reinterpret_cast<float2*>(outz + (size_t)(row + 8) * Dd + col) =
                make_float2(acc[mt][nt][2], acc[mt][nt][3]);
        }
}

// ---------------------------------------------------------------------------
// 3) Finalize (8-slice sum, 4 c's per thread)
// ---------------------------------------------------------------------------
#define C4 (Cc / 4)   // 250
__global__ __launch_bounds__(128) void finalize(const float* __restrict__ lmbda,
                                                const float* __restrict__ scale,
                                                float* __restrict__ out) {
    int idx = blockIdx.x * 128 + threadIdx.x;
    if (idx >= Bb * C4) return;
    int b = idx / C4;
    int c = (idx - b * C4) * 4;

    float4 s = make_float4(0.f, 0.f, 0.f, 0.f);
#pragma unroll
    for (int z = 0; z < KS; z++) {
        float4 p = *reinterpret_cast<const float4*>(
            g_part + ((size_t)z * Bb + b) * Dd + c);
        s.x += p.x; s.y += p.y; s.z += p.z; s.w += p.w;
    }
    float4 qc = *reinterpret_cast<const float4*>(g_q + c);
    float4 bdc = *reinterpret_cast<const float4*>(g_bd + c);
    float qb = g_q[Cc + b];
    float bdb = g_bd[Cc + b];
    float lm = *lmbda;
    float sc = *scale;
    float4 o;
    {
        float quad = qb + qc.x - 2.f * s.x;
        float bd = bdb - bdc.x;
        o.x = -sc * (sqrtf(quad + 1e-6f) + lm * sqrtf(bd * bd + 1e-6f));
    }
    {
        float quad = qb + qc.y - 2.f * s.y;
        float bd = bdb - bdc.y;
        o.y = -sc * (sqrtf(quad + 1e-6f) + lm * sqrtf(bd * bd + 1e-6f));
    }
    {
        float quad = qb + qc.z - 2.f * s.z;
        float bd = bdb - bdc.z;
        o.z = -sc * (sqrtf(quad + 1e-6f) + lm * sqrtf(bd * bd + 1e-6f));
    }
    {
        float quad = qb + qc.w - 2.f * s.w;
        float bd = bdb - bdc.w;
        o.w = -sc * (sqrtf(quad + 1e-6f) + lm * sqrtf(bd * bd + 1e-6f));
    }
    *reinterpret_cast<float4*>(out + (size_t)b * Cc + c) = o;
}

// ---------------------------------------------------------------------------
extern "C" void kernel_launch(void* const* d_in, const int* in_sizes, int n_in,
                              void* d_out, int out_size) {
    const float *x = nullptr, *mu = nullptr, *beta = nullptr, *L = nullptr;
    const float *lmbda = nullptr, *scale = nullptr;
    for (int i = 0; i < n_in; i++) {
        const float* p = (const float*)d_in[i];
        switch (in_sizes[i]) {
            case Bb * Dd:  x = p; break;
            case Cc * Dd:  mu = p; break;
            case Dd:       beta = p; break;
            case Dd * Dd:  L = p; break;
            case 1:        if (!lmbda) lmbda = p; else scale = p; break;
            default: break;
        }
    }

    prep<<<MP + 1024, 256>>>(x, mu, beta, L);
    gemm_ma_mma<<<dim3(MP / 64, Dd / 64), 128>>>();
    dot_mma<<<dim3(Bb / 64, Dd / 64, KS), 128>>>();
    finalize<<<(Bb * C4 + 127) / 128, 128>>>(lmbda, scale, (float*)d_out);
}

// round 13
// speedup vs baseline: 1.1913x; 1.0933x over previous
#include <cuda_runtime.h>
#include <cuda_bf16.h>
#include <cstdint>
#include <stdint.h>
#include <math.h>

// Problem constants
#define Dd 1024   // feature dim
#define Cc 1000   // prototypes
#define Bb 128    // batch
#define RT 1128   // Cc + Bb stacked rows
#define MP 1152   // RT padded to multiple of 64

// Scratch (device globals — no allocation allowed)
__device__ __nv_bfloat16 g_Abf[MP * Dd];   // [mu; x; 0] bf16
__device__ __nv_bfloat16 g_Bbf[Dd * Dd];   // tril(L)^T bf16 [n][k]
__device__ __nv_bfloat16 g_MAbf[MP * Dd];  // MA = [mu;x] @ tril(L)
__device__ float g_q[MP];                  // ||MA_r||^2 + 1e-6||in_r||^2
__device__ float g_bd[RT];                 // beta . in_r

// ---------------------------------------------------------------------------
// helpers
// ---------------------------------------------------------------------------
__device__ __forceinline__ void ldsm_x4(uint32_t* r, uint32_t addr) {
    asm volatile("ldmatrix.sync.aligned.m8n8.x4.shared.b16 {%0,%1,%2,%3}, [%4];\n"
                 : "=r"(r[0]), "=r"(r[1]), "=r"(r[2]), "=r"(r[3]) : "r"(addr));
}

__device__ __forceinline__ void mma_bf16(float* d, const uint32_t* a,
                                         uint32_t b0, uint32_t b1) {
    asm volatile(
        "mma.sync.aligned.m16n8k16.row.col.f32.bf16.bf16.f32 "
        "{%0,%1,%2,%3}, {%4,%5,%6,%7}, {%8,%9}, {%0,%1,%2,%3};\n"
        : "+f"(d[0]), "+f"(d[1]), "+f"(d[2]), "+f"(d[3])
        : "r"(a[0]), "r"(a[1]), "r"(a[2]), "r"(a[3]), "r"(b0), "r"(b1));
}

// ---------------------------------------------------------------------------
// 0) prep (block-range dispatch):
//    [0, MP):        bf16 convert row of [mu;x;0] + input stats (seed g_q, g_bd)
//    [MP, MP+1024):  tril+transpose 32x32 tile of L (skipping never-read tiles)
// ---------------------------------------------------------------------------
__global__ __launch_bounds__(256) void prep(const float* __restrict__ x,
                                            const float* __restrict__ mu,
                                            const float* __restrict__ beta,
                                            const float* __restrict__ L) {
    int bid = blockIdx.x;
    int tid = threadIdx.x;

    if (bid < MP) {
        int r = bid;
        int k = tid * 4;
        float4 v = make_float4(0.f, 0.f, 0.f, 0.f);
        if (r < Cc)      v = *reinterpret_cast<const float4*>(mu + (size_t)r * Dd + k);
        else if (r < RT) v = *reinterpret_cast<const float4*>(x + (size_t)(r - Cc) * Dd + k);
        __nv_bfloat162 p0 = __floats2bfloat162_rn(v.x, v.y);
        __nv_bfloat162 p1 = __floats2bfloat162_rn(v.z, v.w);
        uint2 o;
        o.x = *reinterpret_cast<uint32_t*>(&p0);
        o.y = *reinterpret_cast<uint32_t*>(&p1);
        *reinterpret_cast<uint2*>(g_Abf + (size_t)r * Dd + k) = o;

        if (r >= RT) {
            if (tid == 0) g_q[r] = 0.f;
            return;
        }

        float4 b4 = *reinterpret_cast<const float4*>(beta + k);
        float sin_ = v.x * v.x + v.y * v.y + v.z * v.z + v.w * v.w;
        float sb = b4.x * v.x + b4.y * v.y + b4.z * v.z + b4.w * v.w;
#pragma unroll
        for (int off = 16; off > 0; off >>= 1) {
            sin_ += __shfl_xor_sync(0xFFFFFFFFu, sin_, off);
            sb += __shfl_xor_sync(0xFFFFFFFFu, sb, off);
        }
        __shared__ float red[2][8];
        int wid = tid >> 5, lane = tid & 31;
        if (lane == 0) { red[0][wid] = sin_; red[1][wid] = sb; }
        __syncthreads();
        if (tid == 0) {
            float t0 = 0.f, t1 = 0.f;
#pragma unroll
            for (int wq = 0; wq < 8; wq++) { t0 += red[0][wq]; t1 += red[1][wq]; }
            g_q[r] = 1e-6f * t0;   // seed; gemm epilogue atomically adds ||MA||^2
            g_bd[r] = t1;
        }
    } else {
        int tileId = bid - MP;
        int bx = (tileId & 31) * 32;   // k base
        int by = (tileId >> 5) * 32;   // n base
        // gemm reads g_Bbf[n][k] only for k >= 64*floor(n/64): skip dead tiles
        if (bx < ((by >> 6) << 6)) return;
        __shared__ float t[32][33];
        int tx = tid & 31, ty = tid >> 5;  // 32 x 8
#pragma unroll
        for (int i = ty; i < 32; i += 8)
            t[i][tx] = L[(size_t)(bx + i) * Dd + by + tx];
        __syncthreads();
#pragma unroll
        for (int i = ty; i < 32; i += 8) {
            int n = by + i, k = bx + tx;
            float v = (k >= n) ? t[tx][i] : 0.f;
            g_Bbf[(size_t)n * Dd + k] = __float2bfloat16(v);
        }
    }
}

// ---------------------------------------------------------------------------
// 1) gemm_ma_mma (R7-proven register-prefetch engine, verbatim):
//    g_MAbf[m][n] = sum_k g_Abf[m][k] * g_Bbf[n][k]  (NT bf16 HMMA)
//    BM=BN=64, BK=32, 128 thr, 2x2 warps, warp tile 32x32, triangular K-skip.
//    Epilogue: bf16 store + atomic row-norm into g_q.
// ---------------------------------------------------------------------------
__global__ __launch_bounds__(128) void gemm_ma_mma() {
    __shared__ __align__(16) __nv_bfloat16 As[64][40];
    __shared__ __align__(16) __nv_bfloat16 Bs[64][40];
    int bm = blockIdx.x * 64;
    int bn = blockIdx.y * 64;
    int tid = threadIdx.x;
    int lane = tid & 31, w = tid >> 5;
    int wm = (w & 1) * 32, wn = (w >> 1) * 32;

    int lr = tid >> 1;             // 0..63 (tile row)
    int lk = (tid & 1) * 16;       // 0 / 16 (bf16 units)
    const __nv_bfloat16* aptr = g_Abf + (size_t)(bm + lr) * Dd + lk;
    const __nv_bfloat16* bptr = g_Bbf + (size_t)(bn + lr) * Dd + lk;

    float acc[2][4][4];
#pragma unroll
    for (int mt = 0; mt < 2; mt++)
#pragma unroll
        for (int nt = 0; nt < 4; nt++)
#pragma unroll
            for (int e = 0; e < 4; e++) acc[mt][nt][e] = 0.f;

    uint32_t aA[2], bA[2];
#pragma unroll
    for (int t2 = 0; t2 < 2; t2++) {
        aA[t2] = (uint32_t)__cvta_generic_to_shared(
            &As[wm + t2 * 16 + (lane & 15)][(lane >> 4) * 8]);
        bA[t2] = (uint32_t)__cvta_generic_to_shared(
            &Bs[wn + t2 * 16 + (lane & 15)][(lane >> 4) * 8]);
    }

    int kstart = bn;  // tril skip: L^T[n][k] = 0 for k < n
    uint4 pa0 = *reinterpret_cast<const uint4*>(aptr + kstart);
    uint4 pa1 = *reinterpret_cast<const uint4*>(aptr + kstart + 8);
    uint4 pb0 = *reinterpret_cast<const uint4*>(bptr + kstart);
    uint4 pb1 = *reinterpret_cast<const uint4*>(bptr + kstart + 8);

    for (int k0 = kstart; k0 < Dd; k0 += 32) {
        *reinterpret_cast<uint4*>(&As[lr][lk]) = pa0;
        *reinterpret_cast<uint4*>(&As[lr][lk + 8]) = pa1;
        *reinterpret_cast<uint4*>(&Bs[lr][lk]) = pb0;
        *reinterpret_cast<uint4*>(&Bs[lr][lk + 8]) = pb1;
        __syncthreads();
        if (k0 + 32 < Dd) {
            pa0 = *reinterpret_cast<const uint4*>(aptr + k0 + 32);
            pa1 = *reinterpret_cast<const uint4*>(aptr + k0 + 40);
            pb0 = *reinterpret_cast<const uint4*>(bptr + k0 + 32);
            pb1 = *reinterpret_cast<const uint4*>(bptr + k0 + 40);
        }
#pragma unroll
        for (int ks = 0; ks < 2; ks++) {
            uint32_t off = (uint32_t)(ks * 32);
            uint32_t a0[4], a1[4], br0[4], br1[4];
            ldsm_x4(a0, aA[0] + off);
            ldsm_x4(a1, aA[1] + off);
            ldsm_x4(br0, bA[0] + off);
            ldsm_x4(br1, bA[1] + off);
#pragma unroll
            for (int mt = 0; mt < 2; mt++) {
                uint32_t* a = mt ? a1 : a0;
                mma_bf16(acc[mt][0], a, br0[0], br0[2]);
                mma_bf16(acc[mt][1], a, br0[1], br0[3]);
                mma_bf16(acc[mt][2], a, br1[0], br1[2]);
                mma_bf16(acc[mt][3], a, br1[1], br1[3]);
            }
        }
        __syncthreads();
    }

    int mrow = lane >> 2;
    int ncol = (lane & 3) * 2;
#pragma unroll
    for (int mt = 0; mt < 2; mt++) {
        float s0 = 0.f, s1 = 0.f;
        int row = bm + wm + mt * 16 + mrow;
#pragma unroll
        for (int nt = 0; nt < 4; nt++) {
            int col = bn + wn + nt * 8 + ncol;
            __nv_bfloat162 lo = __floats2bfloat162_rn(acc[mt][nt][0], acc[mt][nt][1]);
            __nv_bfloat162 hi = __floats2bfloat162_rn(acc[mt][nt][2], acc[mt][nt][3]);
            *reinterpret_cast<__nv_bfloat162*>(g_MAbf + (size_t)row * Dd + col) = lo;
            *reinterpret_cast<__nv_bfloat162*>(g_MAbf + (size_t)(row + 8) * Dd + col) = hi;
            float l0 = __bfloat162float(lo.x), l1 = __bfloat162float(lo.y);
            float h0 = __bfloat162float(hi.x), h1 = __bfloat162float(hi.y);
            s0 += l0 * l0 + l1 * l1;
            s1 += h0 * h0 + h1 * h1;
        }
        s0 += __shfl_xor_sync(0xFFFFFFFFu, s0, 1);
        s0 += __shfl_xor_sync(0xFFFFFFFFu, s0, 2);
        s1 += __shfl_xor_sync(0xFFFFFFFFu, s1, 1);
        s1 += __shfl_xor_sync(0xFFFFFFFFu, s1, 2);
        if ((lane & 3) == 0) {
            atomicAdd(&g_q[row], s0);
            atomicAdd(&g_q[row + 8], s1);
        }
    }
}

// ---------------------------------------------------------------------------
// 2) dot_fused: FULL-K cross dot + final output, no split-K, no g_part.
//    32x32 tile per block (grid 4 x 32 = 128 blocks), 4 warps warp-split-K:
//    per 128-wide k-iteration, warp w covers k-quarter [w*32, w*32+32).
//    Partials reduced via smem; epilogue computes out[b][c] directly.
// ---------------------------------------------------------------------------
__global__ __launch_bounds__(128) void dot_fused(const float* __restrict__ lmbda,
                                                 const float* __restrict__ scale,
                                                 float* __restrict__ out) {
    __shared__ __align__(16) __nv_bfloat16 As[32][136];
    __shared__ __align__(16) __nv_bfloat16 Bs[32][136];
    __shared__ float red[4][32][32];

    int bm = blockIdx.x * 32;                // b offset
    int bn = blockIdx.y * 32;                // c offset (padded to 1024)
    int tid = threadIdx.x;
    int lane = tid & 31, w = tid >> 5;       // warp = k-quarter owner

    // load mapping: 32 rows x 128 k, 4 threads/row, 32 elems (4 uint4) each
    int lrow = tid >> 2;                     // 0..31
    int lkq = (tid & 3) * 32;                // 0,32,64,96
    const __nv_bfloat16* aptr = g_MAbf + (size_t)(Cc + bm + lrow) * Dd + lkq;
    const __nv_bfloat16* bptr = g_MAbf + (size_t)(bn + lrow) * Dd + lkq;

    float acc[2][4][4];
#pragma unroll
    for (int mt = 0; mt < 2; mt++)
#pragma unroll
        for (int nt = 0; nt < 4; nt++)
#pragma unroll
            for (int e = 0; e < 4; e++) acc[mt][nt][e] = 0.f;

    // frag addresses: warp w reads its k-quarter cols [w*32, w*32+32)
    uint32_t aA[2], bA[2];
#pragma unroll
    for (int t2 = 0; t2 < 2; t2++) {
        aA[t2] = (uint32_t)__cvta_generic_to_shared(
            &As[t2 * 16 + (lane & 15)][w * 32 + (lane >> 4) * 8]);
        bA[t2] = (uint32_t)__cvta_generic_to_shared(
            &Bs[t2 * 16 + (lane & 15)][w * 32 + (lane >> 4) * 8]);
    }

    uint4 pa[4], pb[4];
#pragma unroll
    for (int j = 0; j < 4; j++) {
        pa[j] = *reinterpret_cast<const uint4*>(aptr + j * 8);
        pb[j] = *reinterpret_cast<const uint4*>(bptr + j * 8);
    }

#pragma unroll 1
    for (int it = 0; it < 8; ++it) {         // 8 x 128 = K 1024
#pragma unroll
        for (int j = 0; j < 4; j++) {
            *reinterpret_cast<uint4*>(&As[lrow][lkq + j * 8]) = pa[j];
            *reinterpret_cast<uint4*>(&Bs[lrow][lkq + j * 8]) = pb[j];
        }
        __syncthreads();
        if (it + 1 < 8) {
            int k = (it + 1) * 128;
#pragma unroll
            for (int j = 0; j < 4; j++) {
                pa[j] = *reinterpret_cast<const uint4*>(aptr + k + j * 8);
                pb[j] = *reinterpret_cast<const uint4*>(bptr + k + j * 8);
            }
        }
#pragma unroll
        for (int ks = 0; ks < 2; ks++) {     // warp's 32-k quarter = 2 ks steps
            uint32_t off = (uint32_t)(ks * 32);   // 16 elems * 2B
            uint32_t a0[4], a1[4], br0[4], br1[4];
            ldsm_x4(a0, aA[0] + off);
            ldsm_x4(a1, aA[1] + off);
            ldsm_x4(br0, bA[0] + off);
            ldsm_x4(br1, bA[1] + off);
#pragma unroll
            for (int mt = 0; mt < 2; mt++) {
                uint32_t* a = mt ? a1 : a0;
                mma_bf16(acc[mt][0], a, br0[0], br0[2]);
                mma_bf16(acc[mt][1], a, br0[1], br0[3]);
                mma_bf16(acc[mt][2], a, br1[0], br1[2]);
                mma_bf16(acc[mt][3], a, br1[1], br1[3]);
            }
        }
        __syncthreads();
    }

    // ---- reduce 4 warp partials via smem ----
    int mrow = lane >> 2;
    int ncol = (lane & 3) * 2;
#pragma unroll
    for (int mt = 0; mt < 2; mt++)
#pragma unroll
        for (int nt = 0; nt < 4; nt++) {
            int r0 = mt * 16 + mrow;
            int c0 = nt * 8 + ncol;
            red[w][r0][c0] = acc[mt][nt][0];
            red[w][r0][c0 + 1] = acc[mt][nt][1];
            red[w][r0 + 8][c0] = acc[mt][nt][2];
            red[w][r0 + 8][c0 + 1] = acc[mt][nt][3];
        }
    __syncthreads();

    // ---- fused finalize: thread t -> row t/4, cols (t%4)*8 .. +8 ----
    {
        int r = tid >> 2;
        int cb = (tid & 3) * 8;
        int b = bm + r;
        float qb = g_q[Cc + b];
        float bdb = g_bd[Cc + b];
        float lm = *lmbda;
        float sc = *scale;
        float* orow = out + (size_t)b * Cc;
#pragma unroll
        for (int j = 0; j < 8; j++) {
            int cl = cb + j;
            int c = bn + cl;
            if (c >= Cc) break;
            float s = red[0][r][cl] + red[1][r][cl] + red[2][r][cl] + red[3][r][cl];
            float quad = qb + g_q[c] - 2.f * s;
            float bd = bdb - g_bd[c];
            orow[c] = -sc * (sqrtf(quad + 1e-6f) + lm * sqrtf(bd * bd + 1e-6f));
        }
    }
}

// ---------------------------------------------------------------------------
extern "C" void kernel_launch(void* const* d_in, const int* in_sizes, int n_in,
                              void* d_out, int out_size) {
    const float *x = nullptr, *mu = nullptr, *beta = nullptr, *L = nullptr;
    const float *lmbda = nullptr, *scale = nullptr;
    for (int i = 0; i < n_in; i++) {
        const float* p = (const float*)d_in[i];
        switch (in_sizes[i]) {
            case Bb * Dd:  x = p; break;
            case Cc * Dd:  mu = p; break;
            case Dd:       beta = p; break;
            case Dd * Dd:  L = p; break;
            case 1:        if (!lmbda) lmbda = p; else scale = p; break;
            default: break;
        }
    }

    prep<<<MP + 1024, 256>>>(x, mu, beta, L);
    gemm_ma_mma<<<dim3(MP / 64, Dd / 64), 128>>>();
    dot_fused<<<dim3(Bb / 32, 32), 128>>>(lmbda, scale, (float*)d_out);
}